// round 5
// baseline (speedup 1.0000x reference)
#include <cuda_runtime.h>
#include <cuda_fp16.h>

#define N_IMGS 2
#define C_CH   256
#define HW_DIM 64
#define HWPIX  (HW_DIM * HW_DIM)      // 4096
#define NPIX   (N_IMGS * HWPIX)       // 8192
#define S_STEPS 64
#define EPSV 1e-3f

// ---------------- scratch (device globals: no allocation allowed) ----------
__device__ float g_F[N_IMGS][9];
__device__ uint4 g_feat2h[(size_t)N_IMGS * HWPIX * C_CH / 8];   // 4 MB, (N,HW,C) half

__device__ __forceinline__ double det3cols(const double c0[3], const double c1[3], const double c2[3]) {
    return c0[0]*(c1[1]*c2[2]-c1[2]*c2[1])
         - c0[1]*(c1[0]*c2[2]-c1[2]*c2[0])
         + c0[2]*(c1[0]*c2[1]-c1[1]*c2[0]);
}

// ---------------- fused prep: block 0 computes F (warp-parallel fp64),
// ---------------- blocks 1..2048 transpose+convert feat2 to (N,HW,C) half --
__global__ __launch_bounds__(256) void prep_kernel(const float* __restrict__ feat2,
                                                   const float* __restrict__ P1g,
                                                   const float* __restrict__ P2g) {
    __shared__ float tile[32][33];
    __shared__ double s_v[N_IMGS][4];
    __shared__ double s_e2[N_IMGS][3];
    __shared__ double s_G[N_IMGS][9];
    __shared__ double s_Gi[N_IMGS][9];
    __shared__ double s_pinv[N_IMGS][12];
    __shared__ double s_B[N_IMGS][9];
    __shared__ double s_rn[N_IMGS], s_rd[N_IMGS];

    if (blockIdx.x == 0) {
        if (threadIdx.y != 0) return;
        int lane = threadIdx.x;
        int n = lane >> 4;
        int r = lane & 15;
        double p1[3][4], p2[3][4];
        #pragma unroll
        for (int i = 0; i < 3; i++)
            #pragma unroll
            for (int j = 0; j < 4; j++) {
                p1[i][j] = (double)P1g[n*12 + i*4 + j];
                p2[i][j] = (double)P2g[n*12 + i*4 + j];
            }
        if (r < 4) {
            double ca[3], cb[3], cc[3];
            int ja = (r == 0) ? 1 : 0;
            int jb = (r <= 1) ? 2 : 1;
            int jc = (r == 3) ? 2 : 3;
            #pragma unroll
            for (int i = 0; i < 3; i++) { ca[i]=p1[i][ja]; cb[i]=p1[i][jb]; cc[i]=p1[i][jc]; }
            double m = det3cols(ca, cb, cc);
            s_v[n][r] = (r & 1) ? -m : m;
        } else if (r < 13) {
            int idx = r - 4;
            int i = idx / 3, k = idx % 3;
            double s = 0.0;
            #pragma unroll
            for (int j = 0; j < 4; j++) s += p1[i][j]*p1[k][j];
            s_G[n][idx] = s;
        }
        __syncwarp();
        if (r == 0) {
            double n2 = s_v[n][0]*s_v[n][0] + s_v[n][1]*s_v[n][1]
                      + s_v[n][2]*s_v[n][2] + s_v[n][3]*s_v[n][3];
            s_rn[n] = 1.0 / sqrt(n2);
        } else if (r == 1) {
            const double* G = s_G[n];
            double detG = G[0]*(G[4]*G[8]-G[5]*G[7])
                        - G[1]*(G[3]*G[8]-G[5]*G[6])
                        + G[2]*(G[3]*G[7]-G[4]*G[6]);
            s_rd[n] = 1.0 / detG;
        }
        __syncwarp();
        if (r < 3) {
            double s = 0.0;
            #pragma unroll
            for (int j = 0; j < 4; j++) s += p2[r][j]*s_v[n][j];
            s_e2[n][r] = s * s_rn[n];
        } else if (r < 12) {
            int idx = r - 3;
            int i = idx / 3, j = idx % 3;
            const double* G = s_G[n];
            int r1 = (j == 0) ? 1 : 0, r2 = (j == 2) ? 1 : 2;
            int c1 = (i == 0) ? 1 : 0, c2 = (i == 2) ? 1 : 2;
            double m = G[r1*3+c1]*G[r2*3+c2] - G[r1*3+c2]*G[r2*3+c1];
            if ((i + j) & 1) m = -m;
            s_Gi[n][idx] = m * s_rd[n];
        }
        __syncwarp();
        if (r < 12) {
            int m_ = r / 3, j = r % 3;
            double s = 0.0;
            #pragma unroll
            for (int k = 0; k < 3; k++) s += p1[k][m_]*s_Gi[n][k*3+j];
            s_pinv[n][r] = s;
        }
        __syncwarp();
        if (r < 9) {
            int i = r / 3, j = r % 3;
            double s = 0.0;
            #pragma unroll
            for (int m_ = 0; m_ < 4; m_++) s += p2[i][m_]*s_pinv[n][m_*3+j];
            s_B[n][r] = s;
        }
        __syncwarp();
        if (r < 9) {
            int i = r / 3, j = r % 3;
            const double* e2 = s_e2[n];
            const double* B  = s_B[n];
            double F;
            if      (i == 0) F = -e2[2]*B[3+j] + e2[1]*B[6+j];
            else if (i == 1) F =  e2[2]*B[j]   - e2[0]*B[6+j];
            else             F = -e2[1]*B[j]   + e2[0]*B[3+j];
            g_F[n][r] = (float)F;
        }
        return;
    }

    int b  = blockIdx.x - 1;
    int n  = b >> 10;
    int ct = ((b >> 7) & 7) * 32;
    int pt = (b & 127) * 32;
    int tx = threadIdx.x, ty = threadIdx.y;
    const float* src = feat2 + (size_t)n * C_CH * HWPIX;
    #pragma unroll
    for (int k = 0; k < 4; k++)
        tile[ty + 8*k][tx] = src[(ct + ty + 8*k) * HWPIX + pt + tx];   // [chan][pix]
    __syncthreads();
    __half* dst = (__half*)g_feat2h + (size_t)n * HWPIX * C_CH;
    int tid = ty * 32 + tx;
    int c2  = tid & 15;
    int pr  = tid >> 4;
    #pragma unroll
    for (int k = 0; k < 2; k++) {
        int row = pr + 16*k;
        __half2 v = __floats2half2_rn(tile[2*c2][row], tile[2*c2+1][row]);
        ((__half2*)(dst + (size_t)(pt + row) * C_CH + ct))[c2] = v;
    }
}

// ---------------- per-pixel line setup helper --------------------------------
__device__ __forceinline__ void pixel_line(int gp, float& sx, float& sy, float& vx, float& vy) {
    int n = gp >> 12;
    int p = gp & 4095;
    float hf = (float)(p >> 6);
    float wf = (float)(p & 63);
    const float* F = g_F[n];
    float a = F[0]*wf + F[1]*hf + F[2];
    float b = F[3]*wf + F[4]*hf + F[5];
    float c = F[6]*wf + F[7]*hf + F[8];
    float sb = (b > 0.f) ? 1.f : ((b < 0.f) ? -1.f : 0.f);
    float sa = (a > 0.f) ? 1.f : ((a < 0.f) ? -1.f : 0.f);
    float db = sb * fmaxf(fabsf(b), EPSV);
    float da = sa * fmaxf(fabsf(a), EPSV);
    const float xmax = 63.f, ymax = 63.f;
    float by1 = -c / db;
    float by2 = -(xmax*a + c) / db;
    float bx0 = -c / da;
    float bx3 = -(ymax*b + c) / da;
    float px[4] = {bx0, 0.f, xmax, bx3};
    float py[4] = {0.f, by1, by2, ymax};
    bool m0 = (bx0 >= EPSV) && (bx0 <  xmax - EPSV);
    bool m1 = (by1 >  EPSV) && (by1 <= ymax - EPSV);
    bool m2 = (by2 >= EPSV) && (by2 <  ymax - EPSV);
    bool m3 = (bx3 >  EPSV) && (bx3 <= xmax - EPSV);
    int nint = (int)m0 + (int)m1 + (int)m2 + (int)m3;
    bool valid2 = nint >= 2;
    bool mm[4];
    if (valid2) { mm[0]=m0; mm[1]=m1; mm[2]=m2; mm[3]=m3; }
    else        { mm[0]=true; mm[1]=true; mm[2]=false; mm[3]=false; }
    int i0 = -1, i1 = -1;
    #pragma unroll
    for (int i = 0; i < 4; i++) {
        if (mm[i]) { if (i0 < 0) i0 = i; else if (i1 < 0) i1 = i; }
    }
    if (valid2) { sx = px[i0]; sy = py[i0]; vx = px[i1]-px[i0]; vy = py[i1]-py[i0]; }
    else        { sx = -10000.f; sy = -10000.f; vx = 0.f; vy = 0.f; }
}

__device__ __forceinline__ void make_wo(int nb, float sx, float sy, float vx, float vy,
                                        int s, uint4& wout, int4& oout) {
    float t  = (float)s / 63.0f;
    float lx = sx + vx * t;
    float ly = sy + vy * t;
    float gx = lx / 63.0f * 2.0f - 1.0f;
    float gy = ly / 63.0f * 2.0f - 1.0f;
    float x  = (gx + 1.0f) * 32.0f - 0.5f;
    float y  = (gy + 1.0f) * 32.0f - 0.5f;
    float x0 = floorf(x), y0 = floorf(y);
    float wx1 = x - x0, wy1 = y - y0;
    bool vx0 = (x0        >= 0.f) && (x0        < 64.f);
    bool vx1 = (x0 + 1.f  >= 0.f) && (x0 + 1.f  < 64.f);
    bool vy0 = (y0        >= 0.f) && (y0        < 64.f);
    bool vy1 = (y0 + 1.f  >= 0.f) && (y0 + 1.f  < 64.f);
    float w0 = (vx0 && vy0) ? (1.f - wx1) * (1.f - wy1) : 0.f;
    float w1 = (vx1 && vy0) ? wx1 * (1.f - wy1)         : 0.f;
    float w2 = (vx0 && vy1) ? (1.f - wx1) * wy1         : 0.f;
    float w3 = (vx1 && vy1) ? wx1 * wy1                 : 0.f;
    wout.x = (unsigned)__half_as_ushort(__float2half_rn(w0)) * 0x10001u;
    wout.y = (unsigned)__half_as_ushort(__float2half_rn(w1)) * 0x10001u;
    wout.z = (unsigned)__half_as_ushort(__float2half_rn(w2)) * 0x10001u;
    wout.w = (unsigned)__half_as_ushort(__float2half_rn(w3)) * 0x10001u;
    int cx0 = (int)fminf(fmaxf(x0,       0.f), 63.f);
    int cx1 = (int)fminf(fmaxf(x0 + 1.f, 0.f), 63.f);
    int cy0 = (int)fminf(fmaxf(y0,       0.f), 63.f);
    int cy1 = (int)fminf(fmaxf(y0 + 1.f, 0.f), 63.f);
    oout.x = (nb + cy0*64 + cx0) * (C_CH/8);
    oout.y = (nb + cy0*64 + cx1) * (C_CH/8);
    oout.z = (nb + cy1*64 + cx0) * (C_CH/8);
    oout.w = (nb + cy1*64 + cx1) * (C_CH/8);
}

// interp 8 channels (uint4 of half2) for one corner set, update 4 accumulators
__device__ __forceinline__ void interp_max(const uint4& wp, const uint4& r0, const uint4& r1,
                                           const uint4& r2, const uint4& r3,
                                           __half2& a0, __half2& a1, __half2& a2, __half2& a3) {
    __half2 w0 = *reinterpret_cast<const __half2*>(&wp.x);
    __half2 w1 = *reinterpret_cast<const __half2*>(&wp.y);
    __half2 w2 = *reinterpret_cast<const __half2*>(&wp.z);
    __half2 w3 = *reinterpret_cast<const __half2*>(&wp.w);
    const __half2* h0 = reinterpret_cast<const __half2*>(&r0);
    const __half2* h1 = reinterpret_cast<const __half2*>(&r1);
    const __half2* h2 = reinterpret_cast<const __half2*>(&r2);
    const __half2* h3 = reinterpret_cast<const __half2*>(&r3);
    __half2 v;
    v = __hmul2(w3, h3[0]); v = __hfma2(w2, h2[0], v); v = __hfma2(w1, h1[0], v); v = __hfma2(w0, h0[0], v);
    a0 = __hmax2(a0, v);
    v = __hmul2(w3, h3[1]); v = __hfma2(w2, h2[1], v); v = __hfma2(w1, h1[1], v); v = __hfma2(w0, h0[1], v);
    a1 = __hmax2(a1, v);
    v = __hmul2(w3, h3[2]); v = __hfma2(w2, h2[2], v); v = __hfma2(w1, h1[2], v); v = __hfma2(w0, h0[2], v);
    a2 = __hmax2(a2, v);
    v = __hmul2(w3, h3[3]); v = __hfma2(w2, h2[3], v); v = __hfma2(w1, h1[3], v); v = __hfma2(w0, h0[3], v);
    a3 = __hmax2(a3, v);
}

// ---------------- fused locs + sampling + max-over-S kernel -----------------
// 1 warp = 2 pixels (interleaved), 8 warps/block -> 16 pixels/block, grid=512.
__global__ __launch_bounds__(256) void sample_kernel(float* __restrict__ out) {
    __shared__ uint4 s_wgt[8][2][S_STEPS];   // 16KB
    __shared__ int4  s_off[8][2][S_STEPS];   // 16KB
    int lane = threadIdx.x;
    int wy   = threadIdx.y;
    int gpA  = blockIdx.x * 16 + wy * 2;
    int gpB  = gpA + 1;

    // ---- phase A: line setup + per-sample weights/offsets for both pixels ----
    {
        float sxA, syA, vxA, vyA, sxB, syB, vxB, vyB;
        pixel_line(gpA, sxA, syA, vxA, vyA);
        pixel_line(gpB, sxB, syB, vxB, vyB);
        int nbA = (gpA >> 12) * HWPIX;
        int nbB = (gpB >> 12) * HWPIX;
        #pragma unroll
        for (int t2 = 0; t2 < 2; t2++) {
            int s = lane + 32*t2;
            uint4 w; int4 o;
            make_wo(nbA, sxA, syA, vxA, vyA, s, w, o);
            s_wgt[wy][0][s] = w; s_off[wy][0][s] = o;
            make_wo(nbB, sxB, syB, vxB, vyB, s, w, o);
            s_wgt[wy][1][s] = w; s_off[wy][1][s] = o;
        }
    }
    __syncwarp();

    // ---- phase B: branchless dual-pixel sample loop ----
    __half2 A0 = __float2half2_rn(-65504.f);
    __half2 A1 = A0, A2 = A0, A3 = A0;
    __half2 B0 = A0, B1 = A0, B2 = A0, B3 = A0;
    const uint4* f = (const uint4*)g_feat2h;
    #pragma unroll 2
    for (int s = 0; s < S_STEPS; s++) {
        uint4 wA = s_wgt[wy][0][s];
        uint4 wB = s_wgt[wy][1][s];
        int4  oA = s_off[wy][0][s];
        int4  oB = s_off[wy][1][s];
        uint4 rA0 = f[oA.x + lane];
        uint4 rA1 = f[oA.y + lane];
        uint4 rA2 = f[oA.z + lane];
        uint4 rA3 = f[oA.w + lane];
        uint4 rB0 = f[oB.x + lane];
        uint4 rB1 = f[oB.y + lane];
        uint4 rB2 = f[oB.z + lane];
        uint4 rB3 = f[oB.w + lane];
        interp_max(wA, rA0, rA1, rA2, rA3, A0, A1, A2, A3);
        interp_max(wB, rB0, rB1, rB2, rB3, B0, B1, B2, B3);
    }

    // ---- stage results (16 pixels x 256 ch floats = 16KB, reuse s_wgt) ----
    __syncthreads();
    float* sOut = (float*)&s_wgt[0][0][0];
    {
        float* rowA = sOut + (wy*2 + 0) * C_CH;
        float* rowB = sOut + (wy*2 + 1) * C_CH;
        float2 t;
        t = __half22float2(A0); rowA[lane*8+0]=t.x; rowA[lane*8+1]=t.y;
        t = __half22float2(A1); rowA[lane*8+2]=t.x; rowA[lane*8+3]=t.y;
        t = __half22float2(A2); rowA[lane*8+4]=t.x; rowA[lane*8+5]=t.y;
        t = __half22float2(A3); rowA[lane*8+6]=t.x; rowA[lane*8+7]=t.y;
        t = __half22float2(B0); rowB[lane*8+0]=t.x; rowB[lane*8+1]=t.y;
        t = __half22float2(B1); rowB[lane*8+2]=t.x; rowB[lane*8+3]=t.y;
        t = __half22float2(B2); rowB[lane*8+4]=t.x; rowB[lane*8+5]=t.y;
        t = __half22float2(B3); rowB[lane*8+6]=t.x; rowB[lane*8+7]=t.y;
    }
    __syncthreads();

    // ---- coalesced store: thread = channel, 16 pixels -> 4x STG.128 ----
    {
        int c   = wy * 32 + lane;          // 0..255
        int gpb = blockIdx.x * 16;
        int nB  = gpb >> 12;
        int pB  = gpb & 4095;
        size_t base = ((size_t)(nB * C_CH + c)) * HWPIX + pB;
        #pragma unroll
        for (int q = 0; q < 4; q++) {
            float4 o4 = make_float4(sOut[(4*q+0)*C_CH + c], sOut[(4*q+1)*C_CH + c],
                                    sOut[(4*q+2)*C_CH + c], sOut[(4*q+3)*C_CH + c]);
            *reinterpret_cast<float4*>(out + base + 4*q) = o4;
        }
    }
}

// ---------------- launch ------------------------------------------------------
extern "C" void kernel_launch(void* const* d_in, const int* in_sizes, int n_in,
                              void* d_out, int out_size) {
    (void)in_sizes; (void)n_in; (void)out_size;
    const float* feat2 = (const float*)d_in[1];
    const float* P1    = (const float*)d_in[2];
    const float* P2    = (const float*)d_in[3];

    prep_kernel<<<2049, dim3(32, 8)>>>(feat2, P1, P2);
    sample_kernel<<<NPIX / 16, dim3(32, 8)>>>((float*)d_out);
}

// round 6
// speedup vs baseline: 1.2511x; 1.2511x over previous
#include <cuda_runtime.h>
#include <cuda_fp16.h>

#define N_IMGS 2
#define C_CH   256
#define HW_DIM 64
#define HWPIX  (HW_DIM * HW_DIM)      // 4096
#define NPIX   (N_IMGS * HWPIX)       // 8192
#define S_STEPS 64
#define EPSV 1e-3f

// ---------------- scratch (device globals: no allocation allowed) ----------
__device__ float g_F[N_IMGS][9];
__device__ uint4 g_feat2h[(size_t)N_IMGS * HWPIX * C_CH / 8];   // 4 MB, (N,HW,C) half

__device__ __forceinline__ double det3cols(const double c0[3], const double c1[3], const double c2[3]) {
    return c0[0]*(c1[1]*c2[2]-c1[2]*c2[1])
         - c0[1]*(c1[0]*c2[2]-c1[2]*c2[0])
         + c0[2]*(c1[0]*c2[1]-c1[1]*c2[0]);
}

// ---------------- fused prep: block 0 computes F (warp-parallel fp64),
// ---------------- blocks 1..2048 transpose+convert feat2 to (N,HW,C) half --
__global__ __launch_bounds__(256) void prep_kernel(const float* __restrict__ feat2,
                                                   const float* __restrict__ P1g,
                                                   const float* __restrict__ P2g) {
    __shared__ float tile[32][33];
    __shared__ double s_v[N_IMGS][4];
    __shared__ double s_e2[N_IMGS][3];
    __shared__ double s_G[N_IMGS][9];
    __shared__ double s_Gi[N_IMGS][9];
    __shared__ double s_pinv[N_IMGS][12];
    __shared__ double s_B[N_IMGS][9];
    __shared__ double s_rn[N_IMGS], s_rd[N_IMGS];

    if (blockIdx.x == 0) {
        if (threadIdx.y != 0) return;
        int lane = threadIdx.x;
        int n = lane >> 4;
        int r = lane & 15;
        double p1[3][4], p2[3][4];
        #pragma unroll
        for (int i = 0; i < 3; i++)
            #pragma unroll
            for (int j = 0; j < 4; j++) {
                p1[i][j] = (double)P1g[n*12 + i*4 + j];
                p2[i][j] = (double)P2g[n*12 + i*4 + j];
            }
        if (r < 4) {
            double ca[3], cb[3], cc[3];
            int ja = (r == 0) ? 1 : 0;
            int jb = (r <= 1) ? 2 : 1;
            int jc = (r == 3) ? 2 : 3;
            #pragma unroll
            for (int i = 0; i < 3; i++) { ca[i]=p1[i][ja]; cb[i]=p1[i][jb]; cc[i]=p1[i][jc]; }
            double m = det3cols(ca, cb, cc);
            s_v[n][r] = (r & 1) ? -m : m;
        } else if (r < 13) {
            int idx = r - 4;
            int i = idx / 3, k = idx % 3;
            double s = 0.0;
            #pragma unroll
            for (int j = 0; j < 4; j++) s += p1[i][j]*p1[k][j];
            s_G[n][idx] = s;
        }
        __syncwarp();
        if (r == 0) {
            double n2 = s_v[n][0]*s_v[n][0] + s_v[n][1]*s_v[n][1]
                      + s_v[n][2]*s_v[n][2] + s_v[n][3]*s_v[n][3];
            s_rn[n] = 1.0 / sqrt(n2);
        } else if (r == 1) {
            const double* G = s_G[n];
            double detG = G[0]*(G[4]*G[8]-G[5]*G[7])
                        - G[1]*(G[3]*G[8]-G[5]*G[6])
                        + G[2]*(G[3]*G[7]-G[4]*G[6]);
            s_rd[n] = 1.0 / detG;
        }
        __syncwarp();
        if (r < 3) {
            double s = 0.0;
            #pragma unroll
            for (int j = 0; j < 4; j++) s += p2[r][j]*s_v[n][j];
            s_e2[n][r] = s * s_rn[n];
        } else if (r < 12) {
            int idx = r - 3;
            int i = idx / 3, j = idx % 3;
            const double* G = s_G[n];
            int r1 = (j == 0) ? 1 : 0, r2 = (j == 2) ? 1 : 2;
            int c1 = (i == 0) ? 1 : 0, c2 = (i == 2) ? 1 : 2;
            double m = G[r1*3+c1]*G[r2*3+c2] - G[r1*3+c2]*G[r2*3+c1];
            if ((i + j) & 1) m = -m;
            s_Gi[n][idx] = m * s_rd[n];
        }
        __syncwarp();
        if (r < 12) {
            int m_ = r / 3, j = r % 3;
            double s = 0.0;
            #pragma unroll
            for (int k = 0; k < 3; k++) s += p1[k][m_]*s_Gi[n][k*3+j];
            s_pinv[n][r] = s;
        }
        __syncwarp();
        if (r < 9) {
            int i = r / 3, j = r % 3;
            double s = 0.0;
            #pragma unroll
            for (int m_ = 0; m_ < 4; m_++) s += p2[i][m_]*s_pinv[n][m_*3+j];
            s_B[n][r] = s;
        }
        __syncwarp();
        if (r < 9) {
            int i = r / 3, j = r % 3;
            const double* e2 = s_e2[n];
            const double* B  = s_B[n];
            double F;
            if      (i == 0) F = -e2[2]*B[3+j] + e2[1]*B[6+j];
            else if (i == 1) F =  e2[2]*B[j]   - e2[0]*B[6+j];
            else             F = -e2[1]*B[j]   + e2[0]*B[3+j];
            g_F[n][r] = (float)F;
        }
        return;
    }

    int b  = blockIdx.x - 1;
    int n  = b >> 10;
    int ct = ((b >> 7) & 7) * 32;
    int pt = (b & 127) * 32;
    int tx = threadIdx.x, ty = threadIdx.y;
    const float* src = feat2 + (size_t)n * C_CH * HWPIX;
    #pragma unroll
    for (int k = 0; k < 4; k++)
        tile[ty + 8*k][tx] = src[(ct + ty + 8*k) * HWPIX + pt + tx];   // [chan][pix]
    __syncthreads();
    __half* dst = (__half*)g_feat2h + (size_t)n * HWPIX * C_CH;
    int tid = ty * 32 + tx;
    int c2  = tid & 15;
    int pr  = tid >> 4;
    #pragma unroll
    for (int k = 0; k < 2; k++) {
        int row = pr + 16*k;
        __half2 v = __floats2half2_rn(tile[2*c2][row], tile[2*c2+1][row]);
        ((__half2*)(dst + (size_t)(pt + row) * C_CH + ct))[c2] = v;
    }
}

// ---------------- fused locs + sampling + max-over-S kernel -----------------
// 1 warp = 1 pixel (all 256 channels), 8 warps/block, grid = 1024.
__global__ __launch_bounds__(256) void sample_kernel(float* __restrict__ out) {
    __shared__ uint4    s_wgt[8][S_STEPS];   // packed half2-dup weights (8KB)
    __shared__ unsigned s_oc [8][S_STEPS];   // packed corners cx0,cy0,cx1,cy1 (2KB)
    int lane = threadIdx.x;               // 0..31
    int wy   = threadIdx.y;               // 0..7 pixel-in-block
    int gp   = blockIdx.x * 8 + wy;
    int n    = gp >> 12;
    int p    = gp & 4095;

    // ---- phase A: epipolar line + per-sample weights/offsets (fp32) ----
    {
        float hf = (float)(p >> 6);
        float wf = (float)(p & 63);
        const float* F = g_F[n];
        float a = F[0]*wf + F[1]*hf + F[2];
        float b = F[3]*wf + F[4]*hf + F[5];
        float c = F[6]*wf + F[7]*hf + F[8];
        float sb = (b > 0.f) ? 1.f : ((b < 0.f) ? -1.f : 0.f);
        float sa = (a > 0.f) ? 1.f : ((a < 0.f) ? -1.f : 0.f);
        float db = sb * fmaxf(fabsf(b), EPSV);
        float da = sa * fmaxf(fabsf(a), EPSV);
        const float xmax = 63.f, ymax = 63.f;
        float by1 = -c / db;
        float by2 = -(xmax*a + c) / db;
        float bx0 = -c / da;
        float bx3 = -(ymax*b + c) / da;
        float px[4] = {bx0, 0.f, xmax, bx3};
        float py[4] = {0.f, by1, by2, ymax};
        bool m0 = (bx0 >= EPSV) && (bx0 <  xmax - EPSV);
        bool m1 = (by1 >  EPSV) && (by1 <= ymax - EPSV);
        bool m2 = (by2 >= EPSV) && (by2 <  ymax - EPSV);
        bool m3 = (bx3 >  EPSV) && (bx3 <= xmax - EPSV);
        int nint = (int)m0 + (int)m1 + (int)m2 + (int)m3;
        bool valid2 = nint >= 2;
        bool mm[4];
        if (valid2) { mm[0]=m0; mm[1]=m1; mm[2]=m2; mm[3]=m3; }
        else        { mm[0]=true; mm[1]=true; mm[2]=false; mm[3]=false; }
        int i0 = -1, i1 = -1;
        #pragma unroll
        for (int i = 0; i < 4; i++) {
            if (mm[i]) { if (i0 < 0) i0 = i; else if (i1 < 0) i1 = i; }
        }
        float sx, sy, vx, vy;
        if (valid2) { sx = px[i0]; sy = py[i0]; vx = px[i1]-px[i0]; vy = py[i1]-py[i0]; }
        else        { sx = -10000.f; sy = -10000.f; vx = 0.f; vy = 0.f; }

        #pragma unroll
        for (int t2 = 0; t2 < 2; t2++) {
            int s = lane + 32*t2;
            float t  = (float)s / 63.0f;
            float lx = sx + vx * t;
            float ly = sy + vy * t;
            float gx = lx / 63.0f * 2.0f - 1.0f;
            float gy = ly / 63.0f * 2.0f - 1.0f;
            float x  = (gx + 1.0f) * 32.0f - 0.5f;
            float y  = (gy + 1.0f) * 32.0f - 0.5f;
            float x0 = floorf(x), y0 = floorf(y);
            float wx1 = x - x0, wy1 = y - y0;
            bool vx0 = (x0        >= 0.f) && (x0        < 64.f);
            bool vx1 = (x0 + 1.f  >= 0.f) && (x0 + 1.f  < 64.f);
            bool vy0 = (y0        >= 0.f) && (y0        < 64.f);
            bool vy1 = (y0 + 1.f  >= 0.f) && (y0 + 1.f  < 64.f);
            float w0 = (vx0 && vy0) ? (1.f - wx1) * (1.f - wy1) : 0.f;
            float w1 = (vx1 && vy0) ? wx1 * (1.f - wy1)         : 0.f;
            float w2 = (vx0 && vy1) ? (1.f - wx1) * wy1         : 0.f;
            float w3 = (vx1 && vy1) ? wx1 * wy1                 : 0.f;
            unsigned u0 = (unsigned)__half_as_ushort(__float2half_rn(w0)) * 0x10001u;
            unsigned u1 = (unsigned)__half_as_ushort(__float2half_rn(w1)) * 0x10001u;
            unsigned u2 = (unsigned)__half_as_ushort(__float2half_rn(w2)) * 0x10001u;
            unsigned u3 = (unsigned)__half_as_ushort(__float2half_rn(w3)) * 0x10001u;
            unsigned cx0 = (unsigned)(int)fminf(fmaxf(x0,       0.f), 63.f);
            unsigned cx1 = (unsigned)(int)fminf(fmaxf(x0 + 1.f, 0.f), 63.f);
            unsigned cy0 = (unsigned)(int)fminf(fmaxf(y0,       0.f), 63.f);
            unsigned cy1 = (unsigned)(int)fminf(fmaxf(y0 + 1.f, 0.f), 63.f);
            s_wgt[wy][s] = make_uint4(u0, u1, u2, u3);
            s_oc [wy][s] = cx0 | (cy0 << 8) | (cx1 << 16) | (cy1 << 24);
        }
    }
    __syncwarp();

    // ---- phase B: branchless sample loop, deep unroll for MLP ----
    __half2 a0 = __float2half2_rn(-65504.f);
    __half2 a1 = a0, a2 = a0, a3 = a0;
    // per-warp base: feature row for this image + this lane's 8-channel slot
    const uint4* fb = (const uint4*)g_feat2h + (size_t)(n * HWPIX) * (C_CH/8) + lane;
    #pragma unroll 4
    for (int s = 0; s < S_STEPS; s++) {
        uint4    wp = s_wgt[wy][s];
        unsigned oc = s_oc [wy][s];
        unsigned cx0 = oc & 0xFFu;
        unsigned cy0 = (oc >> 8)  & 0xFFu;
        unsigned cx1 = (oc >> 16) & 0xFFu;
        unsigned cy1 = oc >> 24;
        unsigned r0 = cy0 * 2048u;   // (cy*64)*(C_CH/8)
        unsigned r1 = cy1 * 2048u;
        unsigned c0 = cx0 * 32u;     // cx*(C_CH/8)
        unsigned c1 = cx1 * 32u;
        uint4 v00 = fb[r0 + c0];
        uint4 v01 = fb[r0 + c1];
        uint4 v10 = fb[r1 + c0];
        uint4 v11 = fb[r1 + c1];
        __half2 w0 = *reinterpret_cast<__half2*>(&wp.x);
        __half2 w1 = *reinterpret_cast<__half2*>(&wp.y);
        __half2 w2 = *reinterpret_cast<__half2*>(&wp.z);
        __half2 w3 = *reinterpret_cast<__half2*>(&wp.w);
        const __half2* h0 = reinterpret_cast<const __half2*>(&v00);
        const __half2* h1 = reinterpret_cast<const __half2*>(&v01);
        const __half2* h2 = reinterpret_cast<const __half2*>(&v10);
        const __half2* h3 = reinterpret_cast<const __half2*>(&v11);
        __half2 v;
        v = __hmul2(w3, h3[0]); v = __hfma2(w2, h2[0], v); v = __hfma2(w1, h1[0], v); v = __hfma2(w0, h0[0], v);
        a0 = __hmax2(a0, v);
        v = __hmul2(w3, h3[1]); v = __hfma2(w2, h2[1], v); v = __hfma2(w1, h1[1], v); v = __hfma2(w0, h0[1], v);
        a1 = __hmax2(a1, v);
        v = __hmul2(w3, h3[2]); v = __hfma2(w2, h2[2], v); v = __hfma2(w1, h1[2], v); v = __hfma2(w0, h0[2], v);
        a2 = __hmax2(a2, v);
        v = __hmul2(w3, h3[3]); v = __hfma2(w2, h2[3], v); v = __hfma2(w1, h1[3], v); v = __hfma2(w0, h0[3], v);
        a3 = __hmax2(a3, v);
    }

    // ---- stage results into shared (reuse s_wgt: 8 pixels x 256 floats) ----
    __syncthreads();
    {
        float* sOutW = (float*)&s_wgt[wy][0];
        float2 t;
        t = __half22float2(a0); sOutW[lane*8 + 0] = t.x; sOutW[lane*8 + 1] = t.y;
        t = __half22float2(a1); sOutW[lane*8 + 2] = t.x; sOutW[lane*8 + 3] = t.y;
        t = __half22float2(a2); sOutW[lane*8 + 4] = t.x; sOutW[lane*8 + 5] = t.y;
        t = __half22float2(a3); sOutW[lane*8 + 6] = t.x; sOutW[lane*8 + 7] = t.y;
    }
    __syncthreads();

    // ---- coalesced store: thread = channel, 8 pixels -> 2x STG.128 ----
    {
        int c   = wy * 32 + lane;          // 0..255
        const float* sOut = (const float*)&s_wgt[0][0];   // [pix*256 + c]
        int gpb = blockIdx.x * 8;
        int nB  = gpb >> 12;
        int pB  = gpb & 4095;
        float4 o1 = make_float4(sOut[0*256 + c], sOut[1*256 + c],
                                sOut[2*256 + c], sOut[3*256 + c]);
        float4 o2 = make_float4(sOut[4*256 + c], sOut[5*256 + c],
                                sOut[6*256 + c], sOut[7*256 + c]);
        size_t base = ((size_t)(nB * C_CH + c)) * HWPIX + pB;
        *reinterpret_cast<float4*>(out + base)     = o1;
        *reinterpret_cast<float4*>(out + base + 4) = o2;
    }
}

// ---------------- launch ------------------------------------------------------
extern "C" void kernel_launch(void* const* d_in, const int* in_sizes, int n_in,
                              void* d_out, int out_size) {
    (void)in_sizes; (void)n_in; (void)out_size;
    const float* feat2 = (const float*)d_in[1];
    const float* P1    = (const float*)d_in[2];
    const float* P2    = (const float*)d_in[3];

    prep_kernel<<<2049, dim3(32, 8)>>>(feat2, P1, P2);
    sample_kernel<<<NPIX / 8, dim3(32, 8)>>>((float*)d_out);
}